// round 17
// baseline (speedup 1.0000x reference)
#include <cuda_runtime.h>
#include <cstdint>

#define LOCN  10000
#define DLOC  128
#define DST   64
#define DSUM  256
#define BB    64
#define SS    128
#define NIDX  (BB * SS)        // 8192 loc entries (with duplicates)
#define NBLK  296              // 2 blocks/SM x 148 SMs

#define CHUNK_V4   250         // float4 per chunk (4000 B)
#define NCHUNK     10          // 2500 / 250
#define RING       3           // chunks in flight per warp
#define WARP_SMEM  (RING * CHUNK_V4 * 16)   // 12000 B
#define BLK_SMEM   (8 * WARP_SMEM)          // 96000 B

// Final Y = relu(A@W + b)*16 for claimed rows (5.12 MB).
__device__ float g_Y[(size_t)LOCN * DLOC];
__device__ int   g_flag[LOCN];     // epoch-tagged claims (never cleared)
__device__ int   g_work;           // work-stealing cursor over loc entries
__device__ int   g_epoch;          // bumped by gather kernel each launch

__device__ __forceinline__ uint32_t smem_u32(const void* p) {
    uint32_t a;
    asm("{ .reg .u64 t; cvta.to.shared.u64 t, %1; cvt.u32.u64 %0, t; }"
        : "=r"(a) : "l"(p));
    return a;
}

__device__ __forceinline__ void cp16(uint32_t dst, const void* src) {
    asm volatile("cp.async.cg.shared.global [%0], [%1], 16;\n"
                 :: "r"(dst), "l"(src));
}
__device__ __forceinline__ void cp_commit() {
    asm volatile("cp.async.commit_group;\n");
}
template <int N>
__device__ __forceinline__ void cp_wait() {
    asm volatile("cp.async.wait_group %0;\n" :: "n"(N));
}

// ---------------------------------------------------------------------------
// Kernel 1: SpMM with inline dedup (round-8 logic) where A is delivered via
// cp.async (LDGSTS) into a per-warp 3-slot smem ring: load issue is
// decoupled from the ballot/FMA processing (no register scoreboard), so the
// LSU streams continuously. Detection/processing identical to round 8.
// ---------------------------------------------------------------------------
__global__ void __launch_bounds__(256, 2) spmm_dedup_kernel(
    const int*   __restrict__ loc,
    const float* __restrict__ A,
    const float* __restrict__ W,
    const float* __restrict__ bias)
{
    extern __shared__ char s_ring[];

    const int warp = threadIdx.x >> 5;
    const int lane = threadIdx.x & 31;
    const int e    = g_epoch + 1;

    char* my = s_ring + warp * WARP_SMEM;
    const float4* slotp[RING];
    uint32_t      slota[RING];
    #pragma unroll
    for (int s = 0; s < RING; ++s) {
        slotp[s] = reinterpret_cast<const float4*>(my + s * CHUNK_V4 * 16);
        slota[s] = smem_u32(my + s * CHUNK_V4 * 16);
    }

    const float4 Z = make_float4(0.f, 0.f, 0.f, 0.f);
    const float b0v = bias[lane];
    const float b1v = bias[lane + 32];
    const float b2v = bias[lane + 64];
    const float b3v = bias[lane + 96];

    for (;;) {
        // Pop a loc entry; claim its row via epoch exchange (lane 0).
        int widx = 0, claimed = 0, row_idx = 0;
        if (lane == 0) {
            widx = atomicAdd(&g_work, 1);
            if (widx < NIDX) {
                row_idx = __ldg(&loc[widx]);
                claimed = (atomicExch(&g_flag[row_idx], e) != e);
            }
        }
        widx    = __shfl_sync(0xffffffffu, widx, 0);
        if (widx >= NIDX) return;
        claimed = __shfl_sync(0xffffffffu, claimed, 0);
        if (!claimed) continue;                        // duplicate row
        row_idx = __shfl_sync(0xffffffffu, row_idx, 0);

        const float4* __restrict__ row =
            reinterpret_cast<const float4*>(A + (size_t)row_idx * LOCN);

        float acc0 = 0.f, acc1 = 0.f, acc2 = 0.f, acc3 = 0.f;

        // Prologue: fill the ring (chunks 0..2).
        #pragma unroll
        for (int c = 0; c < RING; ++c) {
            const float4* src = row + c * CHUNK_V4;
            for (int i = lane; i < CHUNK_V4; i += 32)
                cp16(slota[c] + i * 16, src + i);
            cp_commit();
        }

        for (int c = 0; c < NCHUNK; ++c) {
            // Wait until chunk c has landed (groups retire in FIFO order).
            if      (c <= NCHUNK - RING)     cp_wait<RING - 1>();
            else if (c == NCHUNK - RING + 1) cp_wait<RING - 2>();
            else                             cp_wait<0>();
            __syncwarp();

            const int s = c % RING;
            const float4* __restrict__ sp = slotp[s];
            const int cbase = c * CHUNK_V4;

            #pragma unroll
            for (int k = 0; k < 8; ++k) {
                const int idx = lane + 32 * k;
                const float4 v = (idx < CHUNK_V4) ? sp[idx] : Z;
                const bool nz = (v.x != 0.f) | (v.y != 0.f) |
                                (v.z != 0.f) | (v.w != 0.f);
                unsigned m = __ballot_sync(0xffffffffu, nz);
                while (m) {
                    const int j = __ffs(m) - 1;
                    m &= m - 1;
                    const float vx = __shfl_sync(0xffffffffu, v.x, j);
                    const float vy = __shfl_sync(0xffffffffu, v.y, j);
                    const float vz = __shfl_sync(0xffffffffu, v.z, j);
                    const float vw = __shfl_sync(0xffffffffu, v.w, j);
                    const int n0 = (cbase + k * 32 + j) * 4;

                    const float* __restrict__ Wr = W + (size_t)n0 * DLOC + lane;
                    if (vx != 0.f) {
                        acc0 = fmaf(vx, Wr[0],  acc0);
                        acc1 = fmaf(vx, Wr[32], acc1);
                        acc2 = fmaf(vx, Wr[64], acc2);
                        acc3 = fmaf(vx, Wr[96], acc3);
                    }
                    Wr += DLOC;
                    if (vy != 0.f) {
                        acc0 = fmaf(vy, Wr[0],  acc0);
                        acc1 = fmaf(vy, Wr[32], acc1);
                        acc2 = fmaf(vy, Wr[64], acc2);
                        acc3 = fmaf(vy, Wr[96], acc3);
                    }
                    Wr += DLOC;
                    if (vz != 0.f) {
                        acc0 = fmaf(vz, Wr[0],  acc0);
                        acc1 = fmaf(vz, Wr[32], acc1);
                        acc2 = fmaf(vz, Wr[64], acc2);
                        acc3 = fmaf(vz, Wr[96], acc3);
                    }
                    Wr += DLOC;
                    if (vw != 0.f) {
                        acc0 = fmaf(vw, Wr[0],  acc0);
                        acc1 = fmaf(vw, Wr[32], acc1);
                        acc2 = fmaf(vw, Wr[64], acc2);
                        acc3 = fmaf(vw, Wr[96], acc3);
                    }
                }
            }

            // Reissue this slot with chunk c+RING (after all lanes scanned).
            __syncwarp();
            const int nc = c + RING;
            if (nc < NCHUNK) {
                const float4* src = row + nc * CHUNK_V4;
                for (int i = lane; i < CHUNK_V4; i += 32)
                    cp16(slota[s] + i * 16, src + i);
            }
            cp_commit();   // uniform: empty groups retire immediately
        }

        const float s16 = 16.0f;
        float* __restrict__ y = g_Y + (size_t)row_idx * DLOC + lane;
        y[0]  = fmaxf(acc0 + b0v, 0.f) * s16;
        y[32] = fmaxf(acc1 + b1v, 0.f) * s16;
        y[64] = fmaxf(acc2 + b2v, 0.f) * s16;
        y[96] = fmaxf(acc3 + b3v, 0.f) * s16;
    }
}

// ---------------------------------------------------------------------------
// Kernel 2: full output assembly — one float4 per thread, grid 2560
// (measured-best). Also bumps epoch / resets cursor for the next launch.
// ---------------------------------------------------------------------------
__global__ void __launch_bounds__(256) gather_concat_kernel(
    const int*   __restrict__ loc,
    const int*   __restrict__ st,
    const int*   __restrict__ ed,
    const float* __restrict__ emb_st,
    const float* __restrict__ emb_ed,
    float4*      __restrict__ out)
{
    constexpr int N1V = BB * SS * DSUM / 4;          // 524288 float4
    constexpr int NTV = N1V + BB * SS * DST / 4;     // 655360 float4

    const int idx = blockIdx.x * blockDim.x + threadIdx.x;
    if (idx >= NTV) return;

    if (idx == 0) {
        g_epoch = g_epoch + 1;
        g_work  = 0;
    }

    const float4* __restrict__ Yv  = reinterpret_cast<const float4*>(g_Y);
    const float4* __restrict__ stv = reinterpret_cast<const float4*>(emb_st);
    const float4* __restrict__ edv = reinterpret_cast<const float4*>(emb_ed);
    const float s = 16.0f;

    float4 r;
    if (idx < N1V) {
        const int bs = idx >> 6;
        const int d4 = idx & 63;
        if (d4 < 32) {                               // loc (pre-scaled)
            r = Yv[(size_t)loc[bs] * 32 + d4];
        } else if (d4 < 48) {                        // st
            r = stv[st[bs] * 16 + (d4 - 32)];
            r.x *= s; r.y *= s; r.z *= s; r.w *= s;
        } else {                                     // ed
            r = edv[ed[bs] * 16 + (d4 - 48)];
            r.x *= s; r.y *= s; r.z *= s; r.w *= s;
        }
    } else {
        const int j  = idx - N1V;
        const int bs = j >> 4;
        const int d4 = j & 15;
        const int ss = bs & (SS - 1);
        const int yt = (ss < SS - 1) ? st[bs + 1] : 0;
        r = stv[yt * 16 + d4];                       // res_yt NOT scaled
    }
    out[idx] = r;
}

extern "C" void kernel_launch(void* const* d_in, const int* in_sizes, int n_in,
                              void* d_out, int out_size)
{
    const int*   loc    = (const int*)  d_in[0];
    const int*   st     = (const int*)  d_in[1];
    const int*   ed     = (const int*)  d_in[2];
    const float* A      = (const float*)d_in[3];
    const float* W_loc  = (const float*)d_in[4];
    const float* b_loc  = (const float*)d_in[5];
    const float* emb_st = (const float*)d_in[6];
    const float* emb_ed = (const float*)d_in[7];

    // Opt in to 96 KB dynamic smem (idempotent host call; not enqueued).
    cudaFuncSetAttribute(spmm_dedup_kernel,
                         cudaFuncAttributeMaxDynamicSharedMemorySize,
                         BLK_SMEM);

    spmm_dedup_kernel<<<NBLK, 256, BLK_SMEM>>>(loc, A, W_loc, b_loc);

    constexpr int totalv = (BB * SS * DSUM + BB * SS * DST) / 4;
    gather_concat_kernel<<<(totalv + 255) / 256, 256>>>(
        loc, st, ed, emb_st, emb_ed, (float4*)d_out);
}